// round 1
// baseline (speedup 1.0000x reference)
#include <cuda_runtime.h>

#define BB 16
#define HH 96
#define WW 128
#define HWW (HH*WW)          // 12288
#define NPIX (BB*HWW)        // 196608
#define CP 196

// ---------------- device scratch (allocation-free rule: __device__ globals) ----
__device__ float g_Wc1q[CP*96];     // transposed [k][o]
__device__ float g_Wf1q[64*2];      // [o][k]
__device__ float g_Wf2q[32*64];     // [o][k]
__device__ float g_Wdq[128*9];      // [c][ky*3+kx]
__device__ float g_Wpq[128*80];     // transposed [c][o]
__device__ float g_corflo[(size_t)BB*128*HWW];  // concat(cor, flo)

// ---------------- 1) per-tensor int8 symmetric fake quant ---------------------
__global__ void quant_kernel(const float* __restrict__ Wc1,
                             const float* __restrict__ Wf1,
                             const float* __restrict__ Wf2,
                             const float* __restrict__ Wd,
                             const float* __restrict__ Wp) {
    __shared__ float red[256];
    __shared__ float s_scale;
    int t = blockIdx.x;
    const float* src; int n;
    if      (t == 0) { src = Wc1; n = 96*CP;  }
    else if (t == 1) { src = Wf1; n = 64*2;   }
    else if (t == 2) { src = Wf2; n = 32*64;  }
    else if (t == 3) { src = Wd;  n = 128*9;  }
    else             { src = Wp;  n = 80*128; }

    float m = 0.f;
    for (int i = threadIdx.x; i < n; i += 256) m = fmaxf(m, fabsf(src[i]));
    red[threadIdx.x] = m;
    __syncthreads();
    for (int s = 128; s > 0; s >>= 1) {
        if (threadIdx.x < s) red[threadIdx.x] = fmaxf(red[threadIdx.x], red[threadIdx.x+s]);
        __syncthreads();
    }
    if (threadIdx.x == 0) s_scale = fmaxf(red[0], 1e-8f) / 127.f;
    __syncthreads();
    float sc = s_scale;

    for (int i = threadIdx.x; i < n; i += 256) {
        float q = rintf(src[i] / sc);
        q = fminf(fmaxf(q, -127.f), 127.f) * sc;
        if      (t == 0) { int o = i / CP,  k = i % CP;  g_Wc1q[k*96 + o] = q; }
        else if (t == 1) g_Wf1q[i] = q;
        else if (t == 2) g_Wf2q[i] = q;
        else if (t == 3) g_Wdq[i]  = q;
        else             { int o = i / 128, c = i % 128; g_Wpq[c*80 + o] = q; }
    }
}

// ---------------- 2) corr 1x1 conv 196->96 + relu  (channels 0..95) -----------
// blockIdx.y in {0,1}: each block computes 48 of the 96 output channels.
__global__ __launch_bounds__(256) void cor_kernel(const float* __restrict__ corr,
                                                  const float* __restrict__ bc1) {
    __shared__ float ws[CP*48];     // [k][j]
    __shared__ float bs[48];
    const int co = blockIdx.y * 48;
    for (int i = threadIdx.x; i < CP*48; i += 256) {
        int k = i / 48, j = i % 48;
        ws[i] = g_Wc1q[k*96 + co + j];
    }
    if (threadIdx.x < 48) bs[threadIdx.x] = bc1[co + threadIdx.x];
    __syncthreads();

    int p  = blockIdx.x * 256 + threadIdx.x;        // 768*256 == NPIX exactly
    int b  = p / HWW, hw = p % HWW;
    const float* cbase = corr + (size_t)b * CP * HWW + hw;

    float acc[48];
    #pragma unroll
    for (int j = 0; j < 48; j++) acc[j] = bs[j];

    #pragma unroll 1
    for (int k = 0; k < CP; k += 4) {               // CP = 196 = 4*49
        float v0 = __ldg(cbase + (size_t)(k+0) * HWW);
        float v1 = __ldg(cbase + (size_t)(k+1) * HWW);
        float v2 = __ldg(cbase + (size_t)(k+2) * HWW);
        float v3 = __ldg(cbase + (size_t)(k+3) * HWW);
        const float* w0 = ws + (k+0)*48;
        const float* w1 = ws + (k+1)*48;
        const float* w2 = ws + (k+2)*48;
        const float* w3 = ws + (k+3)*48;
        #pragma unroll
        for (int j = 0; j < 48; j++) {
            acc[j] = fmaf(v0, w0[j], acc[j]);
            acc[j] = fmaf(v1, w1[j], acc[j]);
            acc[j] = fmaf(v2, w2[j], acc[j]);
            acc[j] = fmaf(v3, w3[j], acc[j]);
        }
    }

    float* obase = g_corflo + ((size_t)b * 128 + co) * HWW + hw;
    #pragma unroll
    for (int j = 0; j < 48; j++) obase[(size_t)j * HWW] = fmaxf(acc[j], 0.f);
}

// ---------------- 3) flow 1x1 chain 2->64->32 + relu (channels 96..127) -------
__global__ __launch_bounds__(256) void flo_kernel(const float* __restrict__ flow,
                                                  const float* __restrict__ bf1,
                                                  const float* __restrict__ bf2) {
    __shared__ float w1[128], b1[64], w2[2048], b2[32];
    for (int i = threadIdx.x; i < 128;  i += 256) w1[i] = g_Wf1q[i];
    for (int i = threadIdx.x; i < 64;   i += 256) b1[i] = bf1[i];
    for (int i = threadIdx.x; i < 2048; i += 256) w2[i] = g_Wf2q[i];
    for (int i = threadIdx.x; i < 32;   i += 256) b2[i] = bf2[i];
    __syncthreads();

    int p  = blockIdx.x * 256 + threadIdx.x;
    int b  = p / HWW, hw = p % HWW;
    float fx = flow[(size_t)b * 2 * HWW + hw];
    float fy = flow[(size_t)b * 2 * HWW + HWW + hw];

    float acc[32];
    #pragma unroll
    for (int o = 0; o < 32; o++) acc[o] = b2[o];

    #pragma unroll 4
    for (int j = 0; j < 64; j++) {
        float h = fmaxf(fmaf(fx, w1[2*j], fmaf(fy, w1[2*j+1], b1[j])), 0.f);
        #pragma unroll
        for (int o = 0; o < 32; o++) acc[o] = fmaf(h, w2[o*64 + j], acc[o]);
    }

    float* obase = g_corflo + ((size_t)b * 128 + 96) * HWW + hw;
    #pragma unroll
    for (int o = 0; o < 32; o++) obase[(size_t)o * HWW] = fmaxf(acc[o], 0.f);
}

// ---------------- 4) fused depthwise 3x3 + pointwise 128->80 + relu + flow ----
#define TCH 16
#define TILE_ELEMS (6*34)
__global__ __launch_bounds__(128) void dwpw_kernel(const float* __restrict__ flow,
                                                   const float* __restrict__ bp,
                                                   float* __restrict__ out) {
    extern __shared__ float smem[];
    float* wp   = smem;                 // 128*80
    float* wd   = wp + 128*80;          // 128*9
    float* bsh  = wd + 128*9;           // 80
    float* tile = bsh + 80;             // TCH * 6*34

    for (int i = threadIdx.x; i < 128*80; i += 128) wp[i] = g_Wpq[i];
    for (int i = threadIdx.x; i < 128*9;  i += 128) wd[i] = g_Wdq[i];
    if (threadIdx.x < 80) bsh[threadIdx.x] = bp[threadIdx.x];
    __syncthreads();

    // 1536 blocks: b in [0,16), 24 H-tiles x 4 W-tiles
    int blk = blockIdx.x;
    int b   = blk / 96;
    int t   = blk % 96;
    int ty0 = (t / 4) * 4, tx0 = (t % 4) * 32;
    int tx  = threadIdx.x % 32, ty = threadIdx.x / 32;
    int x   = tx0 + tx, y = ty0 + ty;

    float acc[80];
    #pragma unroll
    for (int o = 0; o < 80; o++) acc[o] = bsh[o];

    const float* cfbase = g_corflo + (size_t)b * 128 * HWW;

    for (int c0 = 0; c0 < 128; c0 += TCH) {
        __syncthreads();   // protect tile from previous chunk's readers
        for (int i = threadIdx.x; i < TCH*TILE_ELEMS; i += 128) {
            int cl = i / TILE_ELEMS, r = i % TILE_ELEMS;
            int ry = r / 34, rx = r % 34;
            int gy = ty0 - 1 + ry, gx = tx0 - 1 + rx;
            float v = 0.f;
            if (gy >= 0 && gy < HH && gx >= 0 && gx < WW)
                v = cfbase[(size_t)(c0 + cl) * HWW + gy * WW + gx];
            tile[cl*TILE_ELEMS + r] = v;
        }
        __syncthreads();

        #pragma unroll 2
        for (int cl = 0; cl < TCH; cl++) {
            const float* wdc = wd + (c0 + cl) * 9;
            const float* tl  = tile + cl*TILE_ELEMS + ty*34 + tx;
            float d = 0.f;
            #pragma unroll
            for (int dy = 0; dy < 3; dy++)
                #pragma unroll
                for (int dx = 0; dx < 3; dx++)
                    d = fmaf(tl[dy*34 + dx], wdc[dy*3 + dx], d);
            const float* wpc = wp + (c0 + cl) * 80;
            #pragma unroll
            for (int o = 0; o < 80; o++) acc[o] = fmaf(d, wpc[o], acc[o]);
        }
    }

    float* ob = out + (size_t)b * 82 * HWW + y * WW + x;
    #pragma unroll
    for (int o = 0; o < 80; o++) ob[(size_t)o * HWW] = fmaxf(acc[o], 0.f);
    // flow passthrough -> channels 80, 81
    ob[(size_t)80 * HWW] = flow[((size_t)b * 2 + 0) * HWW + y * WW + x];
    ob[(size_t)81 * HWW] = flow[((size_t)b * 2 + 1) * HWW + y * WW + x];
}

// ---------------- launch --------------------------------------------------------
extern "C" void kernel_launch(void* const* d_in, const int* in_sizes, int n_in,
                              void* d_out, int out_size) {
    const float* flow = (const float*)d_in[0];
    const float* corr = (const float*)d_in[1];
    const float* Wc1  = (const float*)d_in[2];
    const float* bc1  = (const float*)d_in[3];
    const float* Wf1  = (const float*)d_in[4];
    const float* bf1  = (const float*)d_in[5];
    const float* Wf2  = (const float*)d_in[6];
    const float* bf2  = (const float*)d_in[7];
    const float* Wd   = (const float*)d_in[8];
    const float* Wp   = (const float*)d_in[9];
    const float* bp   = (const float*)d_in[10];
    float* out = (float*)d_out;

    static const size_t dwpw_smem =
        (128*80 + 128*9 + 80 + TCH*TILE_ELEMS) * sizeof(float);  // ~58.9 KB
    cudaFuncSetAttribute(dwpw_kernel, cudaFuncAttributeMaxDynamicSharedMemorySize,
                         (int)dwpw_smem);

    quant_kernel<<<5, 256>>>(Wc1, Wf1, Wf2, Wd, Wp);
    dim3 cg(NPIX/256, 2);
    cor_kernel<<<cg, 256>>>(corr, bc1);
    flo_kernel<<<NPIX/256, 256>>>(flow, bf1, bf2);
    dwpw_kernel<<<BB*96, 128, dwpw_smem>>>(flow, bp, out);
}